// round 7
// baseline (speedup 1.0000x reference)
#include <cuda_runtime.h>
#include <math.h>

#define SEQL 512
#define HIDN 512
#define EMBD 345
#define H4T  4096   // 2 dirs * 4H stacked
#define NN   513

// ------------------------- device scratch (static, no allocs) ---------------
__device__ float g_zin[SEQL * H4T];          // per-layer input projections (both dirs)
__device__ float g_seq[2][SEQL * 1024];      // layer output ping-pong: [t][dir*512+u]
__device__ float g_A[NN * 256];
__device__ float g_B[NN * 256];
__device__ float g_S[NN * NN];
__device__ float g_W2T[256 * 128];
__device__ float g_W3T[128 * 64];
__device__ float g_rowloss[NN];
__device__ unsigned g_bar2[2];               // per-direction arrival counters

// ------------------------- helpers ------------------------------------------
__device__ __forceinline__ float tanhap(float x) {
    float y;
    asm("tanh.approx.f32 %0, %1;" : "=f"(y) : "f"(x));
    return y;
}
__device__ __forceinline__ float sigap(float x) {
    return fmaf(tanhap(0.5f * x), 0.5f, 0.5f);
}

// ------------------------- init (every replay) -------------------------------
__global__ void init_kernel() {
    if (threadIdx.x < 2) g_bar2[threadIdx.x] = 0u;
}

__global__ void prep_transpose(const float* __restrict__ W2,
                               const float* __restrict__ W3) {
    int idx = blockIdx.x * 256 + threadIdx.x;
    if (idx < 128 * 256) { int o = idx >> 8, k = idx & 255; g_W2T[k * 128 + o] = W2[idx]; }
    if (idx < 64 * 128)  { int o = idx >> 7, k = idx & 127; g_W3T[k * 64 + o]  = W3[idx]; }
}

// ------------------------- generic C = X @ W^T (+bias) -----------------------
// shiftX: output row m uses X[m-1]; m==0 -> zeros (implements "avail" padding).
__global__ void __launch_bounds__(256) gemm_xt(
    const float* __restrict__ X, const float* __restrict__ W,
    const float* __restrict__ bias, float* __restrict__ C,
    int M, int Nn, int K, int ldx, int ldw, int ldc, int shiftX)
{
    __shared__ float Xs[16][68];
    __shared__ float Ws[16][68];
    int tid = threadIdx.x;
    int tx = tid & 15, ty = tid >> 4;
    int m0 = blockIdx.y * 64, n0 = blockIdx.x * 64;
    float acc[4][4];
#pragma unroll
    for (int i = 0; i < 4; ++i)
#pragma unroll
        for (int j = 0; j < 4; ++j) acc[i][j] = 0.f;

    for (int k0 = 0; k0 < K; k0 += 16) {
#pragma unroll
        for (int l = 0; l < 4; ++l) {
            int idx = tid + l * 256;
            int mm = idx >> 4, kk = idx & 15;
            int gk = k0 + kk;
            float xv = 0.f;
            int gm = m0 + mm;
            if (gk < K) {
                if (shiftX) { if (gm >= 1 && gm < M) xv = X[(size_t)(gm - 1) * ldx + gk]; }
                else if (gm < M) xv = X[(size_t)gm * ldx + gk];
            }
            Xs[kk][mm] = xv;
            int gn = n0 + mm;
            float wv = 0.f;
            if (gk < K && gn < Nn) wv = W[(size_t)gn * ldw + gk];
            Ws[kk][mm] = wv;
        }
        __syncthreads();
#pragma unroll
        for (int kk = 0; kk < 16; ++kk) {
            float a[4], b[4];
#pragma unroll
            for (int i = 0; i < 4; ++i) a[i] = Xs[kk][ty * 4 + i];
#pragma unroll
            for (int j = 0; j < 4; ++j) b[j] = Ws[kk][tx * 4 + j];
#pragma unroll
            for (int i = 0; i < 4; ++i)
#pragma unroll
                for (int j = 0; j < 4; ++j) acc[i][j] += a[i] * b[j];
        }
        __syncthreads();
    }
#pragma unroll
    for (int i = 0; i < 4; ++i) {
        int gm = m0 + ty * 4 + i;
        if (gm >= M) continue;
#pragma unroll
        for (int j = 0; j < 4; ++j) {
            int gn = n0 + tx * 4 + j;
            if (gn < Nn) C[(size_t)gm * ldc + gn] = acc[i][j] + (bias ? bias[gn] : 0.f);
        }
    }
}

// ------------------------- persistent bidirectional LSTM layer --------------
// 128 CTAs x 256 threads. CTA b: dir d = b>>6, owns 8 hidden units u0 = (b&63)*8.
// Thread: row_local = tid>>3 (0..31 = gate*8+unit), seg = tid&7.
// Weights float4-interleaved: w4[j] = Whh[row][32j + 4*seg .. +3].
// Barrier: per-direction monotonic sum counter; each of the 8 gate threads
// does a red.release add (orders its own h store), target = 512 per step.
// All threads poll with ld.acquire (no syncthreads on the arrive/observe path).
// WAR safety: poll(s+1) success requires own-CTA gate arrivals, which happen
// after sync#2(s) -> all warps finished reading h_sh/zbuf for step s.
__global__ void __launch_bounds__(256, 1) lstm_layer(
    const float* __restrict__ zin,   // [512][4096] (dir*2048 + gate*512 + u)
    const float* __restrict__ Whh,   // [2][2048][512]
    float* __restrict__ seq,         // [512][1024] output: [t][dir*512+u]
    unsigned barBase)
{
    __shared__ __align__(16) float h_sh[512];
    __shared__ float zbuf[32];
    __shared__ float c_sh[8];
    int tid = threadIdx.x;
    int d = blockIdx.x >> 6;
    int bb = blockIdx.x & 63;
    int row_local = tid >> 3;
    int seg = tid & 7;
    int unit_local = row_local & 7;
    int gate = row_local >> 3;
    int u0 = bb * 8;
    int row = gate * 512 + u0 + unit_local;
    const float4* wrow4 =
        reinterpret_cast<const float4*>(Whh + ((size_t)d * 2048 + row) * 512);
    float4 w4[16];
#pragma unroll
    for (int j = 0; j < 16; ++j) w4[j] = wrow4[8 * j + seg];
    if (tid < 8) c_sh[tid] = 0.f;
    int zcol = d * 2048 + row;
    unsigned* ctr = &g_bar2[d];
    const float4* h4 = reinterpret_cast<const float4*>(h_sh);
    float2* h_sh2 = reinterpret_cast<float2*>(h_sh);

    for (int s = 0; s < 512; ++s) {
        int t = d ? (511 - s) : s;
        float zi = __ldg(&zin[(size_t)t * H4T + zcol]);   // issued before poll

        if (s > 0) {
            unsigned target = barBase + (unsigned)s * 512u;
            unsigned v;
            do {
                asm volatile("ld.acquire.gpu.global.u32 %0, [%1];"
                             : "=r"(v) : "l"(ctr) : "memory");
            } while (v < target);
            int tp = d ? (t + 1) : (t - 1);
            const float2* hp =
                reinterpret_cast<const float2*>(seq + (size_t)tp * 1024 + d * 512);
            h_sh2[tid] = hp[tid];
        } else {
            h_sh2[tid] = make_float2(0.f, 0.f);
        }
        __syncthreads();                       // sync#1: h_sh complete

        float acc = 0.f;
#pragma unroll
        for (int j = 0; j < 16; ++j) {
            float4 hv = h4[8 * j + seg];
            acc = fmaf(w4[j].x, hv.x, acc);
            acc = fmaf(w4[j].y, hv.y, acc);
            acc = fmaf(w4[j].z, hv.z, acc);
            acc = fmaf(w4[j].w, hv.w, acc);
        }
#pragma unroll
        for (int o = 4; o; o >>= 1) acc += __shfl_down_sync(0xffffffffu, acc, o, 8);
        if (seg == 0) zbuf[row_local] = zi + acc;
        __syncthreads();                       // sync#2: zbuf complete, reads done

        if (tid < 8) {
            float iv = zbuf[tid], fv = zbuf[8 + tid], gv = zbuf[16 + tid], ov = zbuf[24 + tid];
            float c = sigap(fv) * c_sh[tid] + sigap(iv) * tanhap(gv);
            c_sh[tid] = c;
            float h = sigap(ov) * tanhap(c);
            seq[(size_t)t * 1024 + d * 512 + u0 + tid] = h;
            asm volatile("red.release.gpu.global.add.u32 [%0], 1;"
                         :: "l"(ctr) : "memory");
        }
    }
}

// ------------------------- pairwise MLP scorer -------------------------------
__global__ void __launch_bounds__(256) pair_mlp(
    const float* __restrict__ A, const float* __restrict__ B,
    const float* __restrict__ b1, const float* __restrict__ b2,
    const float* __restrict__ b3, const float* __restrict__ W4,
    const float* __restrict__ b4, float* __restrict__ S)
{
    extern __shared__ float sm[];
    float* Ash = sm;                 // 8*260
    float* Bsh = Ash + 8 * 260;      // 8*260
    float* b1s = Bsh + 8 * 260;      // 256
    float* Vsh = b1s + 256;          // 32*68
    float* W2c = Vsh + 32 * 68;      // 32*132
    float* h2s = W2c + 32 * 132;     // 64*132
    float* W3s = h2s + 64 * 132;     // 128*68

    int tid = threadIdx.x;
    int gi0 = blockIdx.y * 8, gj0 = blockIdx.x * 8;

    for (int e = tid; e < 8 * 256; e += 256) {
        int r = e >> 8, c = e & 255;
        int gi = gi0 + r; Ash[r * 260 + c] = (gi < NN) ? A[gi * 256 + c] : 0.f;
        int gj = gj0 + r; Bsh[r * 260 + c] = (gj < NN) ? B[gj * 256 + c] : 0.f;
    }
    b1s[tid] = b1[tid];

    int tpy = tid >> 4, tpx = tid & 15;
    int p0 = tpy * 4;
    float acc[4][8];
#pragma unroll
    for (int i = 0; i < 4; ++i)
#pragma unroll
        for (int j = 0; j < 8; ++j) acc[i][j] = 0.f;

    for (int kc = 0; kc < 256; kc += 32) {
        __syncthreads();
#pragma unroll
        for (int n = 0; n < 8; ++n) {
            int e = tid + n * 256;
            int kk = e >> 6, p = e & 63;
            int pi = p >> 3, pj = p & 7;
            float v = Ash[pi * 260 + kc + kk] + Bsh[pj * 260 + kc + kk] + b1s[kc + kk];
            Vsh[kk * 68 + p] = fmaxf(v, 0.f);
        }
#pragma unroll
        for (int n = 0; n < 16; ++n) {
            int e = tid + n * 256;
            int kk = e >> 7, o = e & 127;
            W2c[kk * 132 + o] = g_W2T[(kc + kk) * 128 + o];
        }
        __syncthreads();
#pragma unroll
        for (int kk = 0; kk < 32; ++kk) {
            float a[4], b[8];
#pragma unroll
            for (int i = 0; i < 4; ++i) a[i] = Vsh[kk * 68 + p0 + i];
#pragma unroll
            for (int j = 0; j < 4; ++j) {
                b[j]     = W2c[kk * 132 + tpx * 4 + j];
                b[4 + j] = W2c[kk * 132 + 64 + tpx * 4 + j];
            }
#pragma unroll
            for (int i = 0; i < 4; ++i)
#pragma unroll
                for (int j = 0; j < 8; ++j) acc[i][j] += a[i] * b[j];
        }
    }
    __syncthreads();
#pragma unroll
    for (int j = 0; j < 4; ++j) {
        float bb0 = b2[tpx * 4 + j], bb1 = b2[64 + tpx * 4 + j];
#pragma unroll
        for (int i = 0; i < 4; ++i) {
            h2s[(p0 + i) * 132 + tpx * 4 + j]       = fmaxf(acc[i][j] + bb0, 0.f);
            h2s[(p0 + i) * 132 + 64 + tpx * 4 + j]  = fmaxf(acc[i][4 + j] + bb1, 0.f);
        }
    }
#pragma unroll
    for (int n = 0; n < 32; ++n) {
        int e = tid + n * 256;
        int k = e >> 6, o = e & 63;
        W3s[k * 68 + o] = g_W3T[k * 64 + o];
    }
    __syncthreads();

    float acc2[4][4];
#pragma unroll
    for (int i = 0; i < 4; ++i)
#pragma unroll
        for (int j = 0; j < 4; ++j) acc2[i][j] = 0.f;
    for (int k = 0; k < 128; ++k) {
        float a[4], b[4];
#pragma unroll
        for (int i = 0; i < 4; ++i) a[i] = h2s[(p0 + i) * 132 + k];
#pragma unroll
        for (int j = 0; j < 4; ++j) b[j] = W3s[k * 68 + tpx * 4 + j];
#pragma unroll
        for (int i = 0; i < 4; ++i)
#pragma unroll
            for (int j = 0; j < 4; ++j) acc2[i][j] += a[i] * b[j];
    }
    float w4v[4], b3v[4];
#pragma unroll
    for (int j = 0; j < 4; ++j) { w4v[j] = W4[tpx * 4 + j]; b3v[j] = b3[tpx * 4 + j]; }
    float partial[4];
#pragma unroll
    for (int i = 0; i < 4; ++i) {
        float p = 0.f;
#pragma unroll
        for (int j = 0; j < 4; ++j) p += fmaxf(acc2[i][j] + b3v[j], 0.f) * w4v[j];
        partial[i] = p;
    }
#pragma unroll
    for (int i = 0; i < 4; ++i)
#pragma unroll
        for (int off = 8; off; off >>= 1)
            partial[i] += __shfl_down_sync(0xffffffffu, partial[i], off, 16);
    if (tpx == 0) {
        float b4v = b4[0];
#pragma unroll
        for (int i = 0; i < 4; ++i) {
            int p = p0 + i;
            int gi = gi0 + (p >> 3), gj = gj0 + (p & 7);
            if (gi < NN && gj < NN) S[gi * NN + gj] = partial[i] + b4v;
        }
    }
}

// ------------------------- loss partials + row softmax -----------------------
__global__ void __launch_bounds__(256) row_softmax(
    const int* __restrict__ heads, float* __restrict__ out)
{
    __shared__ float srow[NN];
    __shared__ float red[256];
    int i = blockIdx.x, tid = threadIdx.x;
    int h = heads[i];
    float lp = 0.f, mx = -1e30f;
    for (int j = tid; j < NN; j += 256) {
        float v = g_S[i * NN + j];
        srow[j] = v;
        float tt = (j == h) ? 100.f : 0.f;
        float dd = v - tt; lp += dd * dd;
        mx = fmaxf(mx, v);
    }
    red[tid] = lp; __syncthreads();
    for (int o = 128; o; o >>= 1) { if (tid < o) red[tid] += red[tid + o]; __syncthreads(); }
    if (tid == 0) g_rowloss[i] = red[0];
    __syncthreads();
    red[tid] = mx; __syncthreads();
    for (int o = 128; o; o >>= 1) { if (tid < o) red[tid] = fmaxf(red[tid], red[tid + o]); __syncthreads(); }
    float m = red[0];
    __syncthreads();
    float se = 0.f;
    for (int j = tid; j < NN; j += 256) { float e = expf(srow[j] - m); srow[j] = e; se += e; }
    red[tid] = se; __syncthreads();
    for (int o = 128; o; o >>= 1) { if (tid < o) red[tid] += red[tid + o]; __syncthreads(); }
    float inv = 1.f / red[0];
    for (int j = tid; j < NN; j += 256) out[1 + i * NN + j] = srow[j] * inv;
}

__global__ void __launch_bounds__(256) finalize_loss(float* __restrict__ out) {
    __shared__ float red[256];
    int tid = threadIdx.x;
    float s = 0.f;
    for (int i = tid; i < NN; i += 256) s += g_rowloss[i];
    red[tid] = s; __syncthreads();
    for (int o = 128; o; o >>= 1) { if (tid < o) red[tid] += red[tid + o]; __syncthreads(); }
    if (tid == 0) out[0] = red[0] / ((float)NN * (float)NN);
}

// ------------------------- launch --------------------------------------------
extern "C" void kernel_launch(void* const* d_in, const int* in_sizes, int n_in,
                              void* d_out, int out_size) {
    const float* x     = (const float*)d_in[0];
    const int*   heads = (const int*)d_in[1];
    const float* Wih0  = (const float*)d_in[2];   // (2,2048,345)
    const float* Whh0  = (const float*)d_in[3];   // (2,2048,512)
    const float* b0    = (const float*)d_in[4];   // (2,2048)
    const float* Wih_r = (const float*)d_in[5];   // (3,2,2048,1024)
    const float* Whh_r = (const float*)d_in[6];   // (3,2,2048,512)
    const float* b_r   = (const float*)d_in[7];   // (3,2,2048)
    const float* W1    = (const float*)d_in[8];   // (256,2048)
    const float* b1    = (const float*)d_in[9];
    const float* W2    = (const float*)d_in[10];  // (128,256)
    const float* b2    = (const float*)d_in[11];
    const float* W3    = (const float*)d_in[12];  // (64,128)
    const float* b3    = (const float*)d_in[13];
    const float* W4    = (const float*)d_in[14];  // (1,64)
    const float* b4    = (const float*)d_in[15];
    float* out = (float*)d_out;

    float* zin; cudaGetSymbolAddress((void**)&zin, g_zin);
    float* seq; cudaGetSymbolAddress((void**)&seq, g_seq);
    float* gA;  cudaGetSymbolAddress((void**)&gA, g_A);
    float* gB;  cudaGetSymbolAddress((void**)&gB, g_B);
    float* gS;  cudaGetSymbolAddress((void**)&gS, g_S);
    float* seq0 = seq;
    float* seq1 = seq + SEQL * 1024;

    static int smem_set = 0;
    const int PAIR_SMEM = (8*260*2 + 256 + 32*68 + 32*132 + 64*132 + 128*68) * 4;
    if (!smem_set) {
        cudaFuncSetAttribute(pair_mlp, cudaFuncAttributeMaxDynamicSharedMemorySize, PAIR_SMEM);
        smem_set = 1;
    }

    init_kernel<<<1, 32>>>();
    prep_transpose<<<128, 256>>>(W2, W3);

    // ---- layer 0 ----
    gemm_xt<<<dim3(64, 8), 256>>>(x, Wih0, b0, zin, 512, 4096, EMBD, EMBD, EMBD, 4096, 0);
    lstm_layer<<<128, 256>>>(zin, Whh0, seq0, 0u);

    // ---- layers 1..3 ----
    for (int l = 1; l <= 3; ++l) {
        const float* Xin = (l & 1) ? seq0 : seq1;
        float* Yout = (l & 1) ? seq1 : seq0;
        const float* Wih = Wih_r + (size_t)(l - 1) * 2 * 2048 * 1024;
        const float* Whh = Whh_r + (size_t)(l - 1) * 2 * 2048 * 512;
        const float* bb  = b_r + (size_t)(l - 1) * 4096;
        gemm_xt<<<dim3(64, 8), 256>>>(Xin, Wih, bb, zin, 512, 4096, 1024, 1024, 1024, 4096, 0);
        lstm_layer<<<128, 256>>>(zin, Whh, Yout, (unsigned)(l * 512 * 512));
    }

    // ---- A/B projections (avail = [zeros; seq1], shift=1) ----
    gemm_xt<<<dim3(4, 9), 256>>>(seq1, W1,        nullptr, gA, NN, 256, 1024, 1024, 2048, 256, 1);
    gemm_xt<<<dim3(4, 9), 256>>>(seq1, W1 + 1024, nullptr, gB, NN, 256, 1024, 1024, 2048, 256, 1);

    // ---- pairwise scorer ----
    pair_mlp<<<dim3(65, 65), 256, PAIR_SMEM>>>(gA, gB, b1, b2, b3, W4, b4, gS);

    // ---- loss + softmax + output ----
    row_softmax<<<NN, 256>>>(heads, out);
    finalize_loss<<<1, 256>>>(out);
}

// round 10
// speedup vs baseline: 1.2882x; 1.2882x over previous
#include <cuda_runtime.h>
#include <math.h>

#define SEQL 512
#define HIDN 512
#define EMBD 345
#define H4T  4096   // 2 dirs * 4H stacked
#define NN   513

// ------------------------- device scratch (static, no allocs) ---------------
__device__ float g_zin[SEQL * H4T];          // per-layer input projections (both dirs)
__device__ float g_seq[2][SEQL * 1024];      // layer output ping-pong: [t][dir*512+u]
__device__ float g_A[NN * 256];
__device__ float g_B[NN * 256];
__device__ float g_S[NN * NN];
__device__ float g_W2T[256 * 128];
__device__ float g_W3T[128 * 64];
__device__ float g_rowloss[NN];
__device__ unsigned g_bar2[2];               // per-direction arrival counters

// ------------------------- helpers ------------------------------------------
__device__ __forceinline__ float tanhap(float x) {
    float y;
    asm("tanh.approx.f32 %0, %1;" : "=f"(y) : "f"(x));
    return y;
}
__device__ __forceinline__ float sigap(float x) {
    return fmaf(tanhap(0.5f * x), 0.5f, 0.5f);
}

// ------------------------- init (every replay) -------------------------------
__global__ void init_kernel() {
    if (threadIdx.x < 2) g_bar2[threadIdx.x] = 0u;
}

__global__ void prep_transpose(const float* __restrict__ W2,
                               const float* __restrict__ W3) {
    int idx = blockIdx.x * 256 + threadIdx.x;
    if (idx < 128 * 256) { int o = idx >> 8, k = idx & 255; g_W2T[k * 128 + o] = W2[idx]; }
    if (idx < 64 * 128)  { int o = idx >> 7, k = idx & 127; g_W3T[k * 64 + o]  = W3[idx]; }
}

// ------------------------- generic C = X @ W^T (+bias) -----------------------
// shiftX: output row m uses X[m-1]; m==0 -> zeros (implements "avail" padding).
__global__ void __launch_bounds__(256) gemm_xt(
    const float* __restrict__ X, const float* __restrict__ W,
    const float* __restrict__ bias, float* __restrict__ C,
    int M, int Nn, int K, int ldx, int ldw, int ldc, int shiftX)
{
    __shared__ float Xs[16][68];
    __shared__ float Ws[16][68];
    int tid = threadIdx.x;
    int tx = tid & 15, ty = tid >> 4;
    int m0 = blockIdx.y * 64, n0 = blockIdx.x * 64;
    float acc[4][4];
#pragma unroll
    for (int i = 0; i < 4; ++i)
#pragma unroll
        for (int j = 0; j < 4; ++j) acc[i][j] = 0.f;

    for (int k0 = 0; k0 < K; k0 += 16) {
#pragma unroll
        for (int l = 0; l < 4; ++l) {
            int idx = tid + l * 256;
            int mm = idx >> 4, kk = idx & 15;
            int gk = k0 + kk;
            float xv = 0.f;
            int gm = m0 + mm;
            if (gk < K) {
                if (shiftX) { if (gm >= 1 && gm < M) xv = X[(size_t)(gm - 1) * ldx + gk]; }
                else if (gm < M) xv = X[(size_t)gm * ldx + gk];
            }
            Xs[kk][mm] = xv;
            int gn = n0 + mm;
            float wv = 0.f;
            if (gk < K && gn < Nn) wv = W[(size_t)gn * ldw + gk];
            Ws[kk][mm] = wv;
        }
        __syncthreads();
#pragma unroll
        for (int kk = 0; kk < 16; ++kk) {
            float a[4], b[4];
#pragma unroll
            for (int i = 0; i < 4; ++i) a[i] = Xs[kk][ty * 4 + i];
#pragma unroll
            for (int j = 0; j < 4; ++j) b[j] = Ws[kk][tx * 4 + j];
#pragma unroll
            for (int i = 0; i < 4; ++i)
#pragma unroll
                for (int j = 0; j < 4; ++j) acc[i][j] += a[i] * b[j];
        }
        __syncthreads();
    }
#pragma unroll
    for (int i = 0; i < 4; ++i) {
        int gm = m0 + ty * 4 + i;
        if (gm >= M) continue;
#pragma unroll
        for (int j = 0; j < 4; ++j) {
            int gn = n0 + tx * 4 + j;
            if (gn < Nn) C[(size_t)gm * ldc + gn] = acc[i][j] + (bias ? bias[gn] : 0.f);
        }
    }
}

// ------------------------- persistent bidirectional LSTM layer --------------
// 128 CTAs x 256 threads. CTA b: dir d = b>>6, owns 8 hidden units u0 = (b&63)*8.
// Thread: row_local = tid>>3 (0..31 = gate*8+unit), seg = tid&7.
// Weights float4-interleaved: w4[j] = Whh[row][32j + 4*seg .. +3].
// Barrier (R6-proven): per-direction monotonic counter. tid0 polls with
// ld.acquire, syncthreads broadcasts. Release: the 8 gate threads (all in
// warp 0) store h, __syncwarp orders those stores, lane 0 red.release adds
// (64 arrivals per step per direction -> no counter serialization).
__global__ void __launch_bounds__(256, 1) lstm_layer(
    const float* __restrict__ zin,   // [512][4096] (dir*2048 + gate*512 + u)
    const float* __restrict__ Whh,   // [2][2048][512]
    float* __restrict__ seq,         // [512][1024] output: [t][dir*512+u]
    unsigned barBase)
{
    __shared__ __align__(16) float h_sh[512];
    __shared__ float zbuf[32];
    __shared__ float c_sh[8];
    int tid = threadIdx.x;
    int d = blockIdx.x >> 6;
    int bb = blockIdx.x & 63;
    int row_local = tid >> 3;
    int seg = tid & 7;
    int unit_local = row_local & 7;
    int gate = row_local >> 3;
    int u0 = bb * 8;
    int row = gate * 512 + u0 + unit_local;
    const float4* wrow4 =
        reinterpret_cast<const float4*>(Whh + ((size_t)d * 2048 + row) * 512);
    float4 w4[16];
#pragma unroll
    for (int j = 0; j < 16; ++j) w4[j] = wrow4[8 * j + seg];
    if (tid < 8) c_sh[tid] = 0.f;
    int zcol = d * 2048 + row;
    unsigned* ctr = &g_bar2[d];
    const float4* h4 = reinterpret_cast<const float4*>(h_sh);
    float2* h_sh2 = reinterpret_cast<float2*>(h_sh);

    for (int s = 0; s < 512; ++s) {
        int t = d ? (511 - s) : s;
        float zi = __ldg(&zin[(size_t)t * H4T + zcol]);   // issued before poll

        if (s > 0) {
            if (tid == 0) {
                unsigned target = barBase + (unsigned)s * 64u;
                unsigned v;
                do {
                    asm volatile("ld.acquire.gpu.global.u32 %0, [%1];"
                                 : "=r"(v) : "l"(ctr) : "memory");
                } while (v < target);
            }
            __syncthreads();                   // sync#0: broadcast poll success
            int tp = d ? (t + 1) : (t - 1);
            const float2* hp =
                reinterpret_cast<const float2*>(seq + (size_t)tp * 1024 + d * 512);
            h_sh2[tid] = hp[tid];
        } else {
            h_sh2[tid] = make_float2(0.f, 0.f);
        }
        __syncthreads();                       // sync#1: h_sh complete

        // matvec: 4 independent accumulator chains (cuts dependent-FMA latency)
        float a0 = 0.f, a1 = 0.f, a2 = 0.f, a3 = 0.f;
#pragma unroll
        for (int j = 0; j < 16; ++j) {
            float4 hv = h4[8 * j + seg];
            a0 = fmaf(w4[j].x, hv.x, a0);
            a1 = fmaf(w4[j].y, hv.y, a1);
            a2 = fmaf(w4[j].z, hv.z, a2);
            a3 = fmaf(w4[j].w, hv.w, a3);
        }
        float acc = (a0 + a1) + (a2 + a3);
#pragma unroll
        for (int o = 4; o; o >>= 1) acc += __shfl_down_sync(0xffffffffu, acc, o, 8);
        if (seg == 0) zbuf[row_local] = zi + acc;
        __syncthreads();                       // sync#2: zbuf complete, h_sh reads done

        if (tid < 32) {                        // warp 0 only
            if (tid < 8) {
                float iv = zbuf[tid], fv = zbuf[8 + tid], gv = zbuf[16 + tid], ov = zbuf[24 + tid];
                float c = sigap(fv) * c_sh[tid] + sigap(iv) * tanhap(gv);
                c_sh[tid] = c;
                float h = sigap(ov) * tanhap(c);
                seq[(size_t)t * 1024 + d * 512 + u0 + tid] = h;
            }
            __syncwarp(0xffffffffu);           // orders the 8 h-stores in warp 0
            if (tid == 0)
                asm volatile("red.release.gpu.global.add.u32 [%0], 1;"
                             :: "l"(ctr) : "memory");
        }
    }
}

// ------------------------- pairwise MLP scorer -------------------------------
__global__ void __launch_bounds__(256) pair_mlp(
    const float* __restrict__ A, const float* __restrict__ B,
    const float* __restrict__ b1, const float* __restrict__ b2,
    const float* __restrict__ b3, const float* __restrict__ W4,
    const float* __restrict__ b4, float* __restrict__ S)
{
    extern __shared__ float sm[];
    float* Ash = sm;                 // 8*260
    float* Bsh = Ash + 8 * 260;      // 8*260
    float* b1s = Bsh + 8 * 260;      // 256
    float* Vsh = b1s + 256;          // 32*68
    float* W2c = Vsh + 32 * 68;      // 32*132
    float* h2s = W2c + 32 * 132;     // 64*132
    float* W3s = h2s + 64 * 132;     // 128*68

    int tid = threadIdx.x;
    int gi0 = blockIdx.y * 8, gj0 = blockIdx.x * 8;

    for (int e = tid; e < 8 * 256; e += 256) {
        int r = e >> 8, c = e & 255;
        int gi = gi0 + r; Ash[r * 260 + c] = (gi < NN) ? A[gi * 256 + c] : 0.f;
        int gj = gj0 + r; Bsh[r * 260 + c] = (gj < NN) ? B[gj * 256 + c] : 0.f;
    }
    b1s[tid] = b1[tid];

    int tpy = tid >> 4, tpx = tid & 15;
    int p0 = tpy * 4;
    float acc[4][8];
#pragma unroll
    for (int i = 0; i < 4; ++i)
#pragma unroll
        for (int j = 0; j < 8; ++j) acc[i][j] = 0.f;

    for (int kc = 0; kc < 256; kc += 32) {
        __syncthreads();
#pragma unroll
        for (int n = 0; n < 8; ++n) {
            int e = tid + n * 256;
            int kk = e >> 6, p = e & 63;
            int pi = p >> 3, pj = p & 7;
            float v = Ash[pi * 260 + kc + kk] + Bsh[pj * 260 + kc + kk] + b1s[kc + kk];
            Vsh[kk * 68 + p] = fmaxf(v, 0.f);
        }
#pragma unroll
        for (int n = 0; n < 16; ++n) {
            int e = tid + n * 256;
            int kk = e >> 7, o = e & 127;
            W2c[kk * 132 + o] = g_W2T[(kc + kk) * 128 + o];
        }
        __syncthreads();
#pragma unroll
        for (int kk = 0; kk < 32; ++kk) {
            float a[4], b[8];
#pragma unroll
            for (int i = 0; i < 4; ++i) a[i] = Vsh[kk * 68 + p0 + i];
#pragma unroll
            for (int j = 0; j < 4; ++j) {
                b[j]     = W2c[kk * 132 + tpx * 4 + j];
                b[4 + j] = W2c[kk * 132 + 64 + tpx * 4 + j];
            }
#pragma unroll
            for (int i = 0; i < 4; ++i)
#pragma unroll
                for (int j = 0; j < 8; ++j) acc[i][j] += a[i] * b[j];
        }
    }
    __syncthreads();
#pragma unroll
    for (int j = 0; j < 4; ++j) {
        float bb0 = b2[tpx * 4 + j], bb1 = b2[64 + tpx * 4 + j];
#pragma unroll
        for (int i = 0; i < 4; ++i) {
            h2s[(p0 + i) * 132 + tpx * 4 + j]       = fmaxf(acc[i][j] + bb0, 0.f);
            h2s[(p0 + i) * 132 + 64 + tpx * 4 + j]  = fmaxf(acc[i][4 + j] + bb1, 0.f);
        }
    }
#pragma unroll
    for (int n = 0; n < 32; ++n) {
        int e = tid + n * 256;
        int k = e >> 6, o = e & 63;
        W3s[k * 68 + o] = g_W3T[k * 64 + o];
    }
    __syncthreads();

    float acc2[4][4];
#pragma unroll
    for (int i = 0; i < 4; ++i)
#pragma unroll
        for (int j = 0; j < 4; ++j) acc2[i][j] = 0.f;
    for (int k = 0; k < 128; ++k) {
        float a[4], b[4];
#pragma unroll
        for (int i = 0; i < 4; ++i) a[i] = h2s[(p0 + i) * 132 + k];
#pragma unroll
        for (int j = 0; j < 4; ++j) b[j] = W3s[k * 68 + tpx * 4 + j];
#pragma unroll
        for (int i = 0; i < 4; ++i)
#pragma unroll
            for (int j = 0; j < 4; ++j) acc2[i][j] += a[i] * b[j];
    }
    float w4v[4], b3v[4];
#pragma unroll
    for (int j = 0; j < 4; ++j) { w4v[j] = W4[tpx * 4 + j]; b3v[j] = b3[tpx * 4 + j]; }
    float partial[4];
#pragma unroll
    for (int i = 0; i < 4; ++i) {
        float p = 0.f;
#pragma unroll
        for (int j = 0; j < 4; ++j) p += fmaxf(acc2[i][j] + b3v[j], 0.f) * w4v[j];
        partial[i] = p;
    }
#pragma unroll
    for (int i = 0; i < 4; ++i)
#pragma unroll
        for (int off = 8; off; off >>= 1)
            partial[i] += __shfl_down_sync(0xffffffffu, partial[i], off, 16);
    if (tpx == 0) {
        float b4v = b4[0];
#pragma unroll
        for (int i = 0; i < 4; ++i) {
            int p = p0 + i;
            int gi = gi0 + (p >> 3), gj = gj0 + (p & 7);
            if (gi < NN && gj < NN) S[gi * NN + gj] = partial[i] + b4v;
        }
    }
}

// ------------------------- loss partials + row softmax -----------------------
__global__ void __launch_bounds__(256) row_softmax(
    const int* __restrict__ heads, float* __restrict__ out)
{
    __shared__ float srow[NN];
    __shared__ float red[256];
    int i = blockIdx.x, tid = threadIdx.x;
    int h = heads[i];
    float lp = 0.f, mx = -1e30f;
    for (int j = tid; j < NN; j += 256) {
        float v = g_S[i * NN + j];
        srow[j] = v;
        float tt = (j == h) ? 100.f : 0.f;
        float dd = v - tt; lp += dd * dd;
        mx = fmaxf(mx, v);
    }
    red[tid] = lp; __syncthreads();
    for (int o = 128; o; o >>= 1) { if (tid < o) red[tid] += red[tid + o]; __syncthreads(); }
    if (tid == 0) g_rowloss[i] = red[0];
    __syncthreads();
    red[tid] = mx; __syncthreads();
    for (int o = 128; o; o >>= 1) { if (tid < o) red[tid] = fmaxf(red[tid], red[tid + o]); __syncthreads(); }
    float m = red[0];
    __syncthreads();
    float se = 0.f;
    for (int j = tid; j < NN; j += 256) { float e = expf(srow[j] - m); srow[j] = e; se += e; }
    red[tid] = se; __syncthreads();
    for (int o = 128; o; o >>= 1) { if (tid < o) red[tid] += red[tid + o]; __syncthreads(); }
    float inv = 1.f / red[0];
    for (int j = tid; j < NN; j += 256) out[1 + i * NN + j] = srow[j] * inv;
}

__global__ void __launch_bounds__(256) finalize_loss(float* __restrict__ out) {
    __shared__ float red[256];
    int tid = threadIdx.x;
    float s = 0.f;
    for (int i = tid; i < NN; i += 256) s += g_rowloss[i];
    red[tid] = s; __syncthreads();
    for (int o = 128; o; o >>= 1) { if (tid < o) red[tid] += red[tid + o]; __syncthreads(); }
    if (tid == 0) out[0] = red[0] / ((float)NN * (float)NN);
}

// ------------------------- launch --------------------------------------------
extern "C" void kernel_launch(void* const* d_in, const int* in_sizes, int n_in,
                              void* d_out, int out_size) {
    const float* x     = (const float*)d_in[0];
    const int*   heads = (const int*)d_in[1];
    const float* Wih0  = (const float*)d_in[2];   // (2,2048,345)
    const float* Whh0  = (const float*)d_in[3];   // (2,2048,512)
    const float* b0    = (const float*)d_in[4];   // (2,2048)
    const float* Wih_r = (const float*)d_in[5];   // (3,2,2048,1024)
    const float* Whh_r = (const float*)d_in[6];   // (3,2,2048,512)
    const float* b_r   = (const float*)d_in[7];   // (3,2,2048)
    const float* W1    = (const float*)d_in[8];   // (256,2048)
    const float* b1    = (const float*)d_in[9];
    const float* W2    = (const float*)d_in[10];  // (128,256)
    const float* b2    = (const float*)d_in[11];
    const float* W3    = (const float*)d_in[12];  // (64,128)
    const float* b3    = (const float*)d_in[13];
    const float* W4    = (const float*)d_in[14];  // (1,64)
    const float* b4    = (const float*)d_in[15];
    float* out = (float*)d_out;

    float* zin; cudaGetSymbolAddress((void**)&zin, g_zin);
    float* seq; cudaGetSymbolAddress((void**)&seq, g_seq);
    float* gA;  cudaGetSymbolAddress((void**)&gA, g_A);
    float* gB;  cudaGetSymbolAddress((void**)&gB, g_B);
    float* gS;  cudaGetSymbolAddress((void**)&gS, g_S);
    float* seq0 = seq;
    float* seq1 = seq + SEQL * 1024;

    static int smem_set = 0;
    const int PAIR_SMEM = (8*260*2 + 256 + 32*68 + 32*132 + 64*132 + 128*68) * 4;
    if (!smem_set) {
        cudaFuncSetAttribute(pair_mlp, cudaFuncAttributeMaxDynamicSharedMemorySize, PAIR_SMEM);
        smem_set = 1;
    }

    init_kernel<<<1, 32>>>();
    prep_transpose<<<128, 256>>>(W2, W3);

    // ---- layer 0 ----
    gemm_xt<<<dim3(64, 8), 256>>>(x, Wih0, b0, zin, 512, 4096, EMBD, EMBD, EMBD, 4096, 0);
    lstm_layer<<<128, 256>>>(zin, Whh0, seq0, 0u);

    // ---- layers 1..3 ----
    for (int l = 1; l <= 3; ++l) {
        const float* Xin = (l & 1) ? seq0 : seq1;
        float* Yout = (l & 1) ? seq1 : seq0;
        const float* Wih = Wih_r + (size_t)(l - 1) * 2 * 2048 * 1024;
        const float* Whh = Whh_r + (size_t)(l - 1) * 2 * 2048 * 512;
        const float* bb  = b_r + (size_t)(l - 1) * 4096;
        gemm_xt<<<dim3(64, 8), 256>>>(Xin, Wih, bb, zin, 512, 4096, 1024, 1024, 1024, 4096, 0);
        lstm_layer<<<128, 256>>>(zin, Whh, Yout, (unsigned)(l * 512 * 64));
    }

    // ---- A/B projections (avail = [zeros; seq1], shift=1) ----
    gemm_xt<<<dim3(4, 9), 256>>>(seq1, W1,        nullptr, gA, NN, 256, 1024, 1024, 2048, 256, 1);
    gemm_xt<<<dim3(4, 9), 256>>>(seq1, W1 + 1024, nullptr, gB, NN, 256, 1024, 1024, 2048, 256, 1);

    // ---- pairwise scorer ----
    pair_mlp<<<dim3(65, 65), 256, PAIR_SMEM>>>(gA, gB, b1, b2, b3, W4, b4, gS);

    // ---- loss + softmax + output ----
    row_softmax<<<NN, 256>>>(heads, out);
    finalize_loss<<<1, 256>>>(out);
}

// round 12
// speedup vs baseline: 1.7391x; 1.3500x over previous
#include <cuda_runtime.h>
#include <math.h>

#define SEQL 512
#define HIDN 512
#define EMBD 345
#define H4T  4096   // 2 dirs * 4H stacked
#define NN   513
#define SENT 0x7fc00000u   // NaN sentinel: h in (-1,1) can never equal this

// ------------------------- device scratch (static, no allocs) ---------------
__device__ float g_zin[SEQL * H4T];          // per-layer input projections (both dirs)
__device__ float g_seq[2][SEQL * 1024];      // layer output ping-pong: [t][dir*512+u]
__device__ float g_A[NN * 256];
__device__ float g_B[NN * 256];
__device__ float g_S[NN * NN];
__device__ float g_W2T[256 * 128];
__device__ float g_W3T[128 * 64];
__device__ float g_rowloss[NN];

// ------------------------- helpers ------------------------------------------
__device__ __forceinline__ float tanhap(float x) {
    float y;
    asm("tanh.approx.f32 %0, %1;" : "=f"(y) : "f"(x));
    return y;
}
__device__ __forceinline__ float sigap(float x) {
    return fmaf(tanhap(0.5f * x), 0.5f, 0.5f);
}

// ------------------------- sentinel fill (before each lstm layer) ------------
__global__ void fill_sentinel(float* __restrict__ buf) {
    buf[blockIdx.x * 1024 + threadIdx.x] = __uint_as_float(SENT);
}

__global__ void prep_transpose(const float* __restrict__ W2,
                               const float* __restrict__ W3) {
    int idx = blockIdx.x * 256 + threadIdx.x;
    if (idx < 128 * 256) { int o = idx >> 8, k = idx & 255; g_W2T[k * 128 + o] = W2[idx]; }
    if (idx < 64 * 128)  { int o = idx >> 7, k = idx & 127; g_W3T[k * 64 + o]  = W3[idx]; }
}

// ------------------------- generic C = X @ W^T (+bias) -----------------------
// shiftX: output row m uses X[m-1]; m==0 -> zeros (implements "avail" padding).
__global__ void __launch_bounds__(256) gemm_xt(
    const float* __restrict__ X, const float* __restrict__ W,
    const float* __restrict__ bias, float* __restrict__ C,
    int M, int Nn, int K, int ldx, int ldw, int ldc, int shiftX)
{
    __shared__ float Xs[16][68];
    __shared__ float Ws[16][68];
    int tid = threadIdx.x;
    int tx = tid & 15, ty = tid >> 4;
    int m0 = blockIdx.y * 64, n0 = blockIdx.x * 64;
    float acc[4][4];
#pragma unroll
    for (int i = 0; i < 4; ++i)
#pragma unroll
        for (int j = 0; j < 4; ++j) acc[i][j] = 0.f;

    for (int k0 = 0; k0 < K; k0 += 16) {
#pragma unroll
        for (int l = 0; l < 4; ++l) {
            int idx = tid + l * 256;
            int mm = idx >> 4, kk = idx & 15;
            int gk = k0 + kk;
            float xv = 0.f;
            int gm = m0 + mm;
            if (gk < K) {
                if (shiftX) { if (gm >= 1 && gm < M) xv = X[(size_t)(gm - 1) * ldx + gk]; }
                else if (gm < M) xv = X[(size_t)gm * ldx + gk];
            }
            Xs[kk][mm] = xv;
            int gn = n0 + mm;
            float wv = 0.f;
            if (gk < K && gn < Nn) wv = W[(size_t)gn * ldw + gk];
            Ws[kk][mm] = wv;
        }
        __syncthreads();
#pragma unroll
        for (int kk = 0; kk < 16; ++kk) {
            float a[4], b[4];
#pragma unroll
            for (int i = 0; i < 4; ++i) a[i] = Xs[kk][ty * 4 + i];
#pragma unroll
            for (int j = 0; j < 4; ++j) b[j] = Ws[kk][tx * 4 + j];
#pragma unroll
            for (int i = 0; i < 4; ++i)
#pragma unroll
                for (int j = 0; j < 4; ++j) acc[i][j] += a[i] * b[j];
        }
        __syncthreads();
    }
#pragma unroll
    for (int i = 0; i < 4; ++i) {
        int gm = m0 + ty * 4 + i;
        if (gm >= M) continue;
#pragma unroll
        for (int j = 0; j < 4; ++j) {
            int gn = n0 + tx * 4 + j;
            if (gn < Nn) C[(size_t)gm * ldc + gn] = acc[i][j] + (bias ? bias[gn] : 0.f);
        }
    }
}

// ------------------------- persistent bidirectional LSTM layer --------------
// 128 CTAs x 256 threads. CTA b: dir d = b>>6, owns 8 hidden units u0 = (b&63)*8.
// Thread: row_local = tid>>3 (0..31 = gate*8+unit), seg = tid&7.
// Weights float4-interleaved: w4[j] = Whh[row][32j + 4*seg .. +3].
// Handshake: NO counter. seq is pre-filled with a NaN sentinel; producers
// st.relaxed.gpu their h values; every consumer thread directly polls its own
// float2 of seq[t -/+ 1] until both lanes are real -> the poll IS the load.
// WAR safety: a thread's poll for step s+1 follows its own sync#2(s), which
// guarantees the whole CTA finished reading h_sh/zbuf for step s.
// Deadlock-free: stores for step s happen before warp0 reaches sync#1(s+1).
__global__ void __launch_bounds__(256, 1) lstm_layer(
    const float* __restrict__ zin,   // [512][4096] (dir*2048 + gate*512 + u)
    const float* __restrict__ Whh,   // [2][2048][512]
    float* __restrict__ seq)         // [512][1024] output: [t][dir*512+u]
{
    __shared__ __align__(16) float h_sh[512];
    __shared__ float zbuf[32];
    __shared__ float c_sh[8];
    int tid = threadIdx.x;
    int d = blockIdx.x >> 6;
    int bb = blockIdx.x & 63;
    int row_local = tid >> 3;
    int seg = tid & 7;
    int unit_local = row_local & 7;
    int gate = row_local >> 3;
    int u0 = bb * 8;
    int row = gate * 512 + u0 + unit_local;
    const float4* wrow4 =
        reinterpret_cast<const float4*>(Whh + ((size_t)d * 2048 + row) * 512);
    float4 w4[16];
#pragma unroll
    for (int j = 0; j < 16; ++j) w4[j] = wrow4[8 * j + seg];
    if (tid < 8) c_sh[tid] = 0.f;
    int zcol = d * 2048 + row;
    const float4* h4 = reinterpret_cast<const float4*>(h_sh);
    float2* h_sh2 = reinterpret_cast<float2*>(h_sh);

    for (int s = 0; s < 512; ++s) {
        int t = d ? (511 - s) : s;
        float zi = __ldg(&zin[(size_t)t * H4T + zcol]);   // issued before poll

        if (s > 0) {
            int tp = d ? (t + 1) : (t - 1);
            const float* hp = seq + (size_t)tp * 1024 + d * 512 + 2 * tid;
            float hx, hy;
            do {
                asm volatile("ld.volatile.global.v2.f32 {%0,%1}, [%2];"
                             : "=f"(hx), "=f"(hy) : "l"(hp));
            } while (__float_as_uint(hx) == SENT || __float_as_uint(hy) == SENT);
            h_sh2[tid] = make_float2(hx, hy);
        } else {
            h_sh2[tid] = make_float2(0.f, 0.f);
        }
        __syncthreads();                       // sync#1: h_sh complete

        // matvec: 4 independent accumulator chains
        float a0 = 0.f, a1 = 0.f, a2 = 0.f, a3 = 0.f;
#pragma unroll
        for (int j = 0; j < 16; ++j) {
            float4 hv = h4[8 * j + seg];
            a0 = fmaf(w4[j].x, hv.x, a0);
            a1 = fmaf(w4[j].y, hv.y, a1);
            a2 = fmaf(w4[j].z, hv.z, a2);
            a3 = fmaf(w4[j].w, hv.w, a3);
        }
        float acc = (a0 + a1) + (a2 + a3);
#pragma unroll
        for (int o = 4; o; o >>= 1) acc += __shfl_down_sync(0xffffffffu, acc, o, 8);
        if (seg == 0) zbuf[row_local] = zi + acc;
        __syncthreads();                       // sync#2: zbuf ready, h_sh reads done

        if (tid < 8) {
            float iv = zbuf[tid], fv = zbuf[8 + tid], gv = zbuf[16 + tid], ov = zbuf[24 + tid];
            float c = sigap(fv) * c_sh[tid] + sigap(iv) * tanhap(gv);
            c_sh[tid] = c;
            float h = sigap(ov) * tanhap(c);
            float* dst = seq + (size_t)t * 1024 + d * 512 + u0 + tid;
            asm volatile("st.relaxed.gpu.global.f32 [%0], %1;"
                         :: "l"(dst), "f"(h) : "memory");
        }
    }
}

// ------------------------- pairwise MLP scorer -------------------------------
__global__ void __launch_bounds__(256) pair_mlp(
    const float* __restrict__ A, const float* __restrict__ B,
    const float* __restrict__ b1, const float* __restrict__ b2,
    const float* __restrict__ b3, const float* __restrict__ W4,
    const float* __restrict__ b4, float* __restrict__ S)
{
    extern __shared__ float sm[];
    float* Ash = sm;                 // 8*260
    float* Bsh = Ash + 8 * 260;      // 8*260
    float* b1s = Bsh + 8 * 260;      // 256
    float* Vsh = b1s + 256;          // 32*68
    float* W2c = Vsh + 32 * 68;      // 32*132
    float* h2s = W2c + 32 * 132;     // 64*132
    float* W3s = h2s + 64 * 132;     // 128*68

    int tid = threadIdx.x;
    int gi0 = blockIdx.y * 8, gj0 = blockIdx.x * 8;

    for (int e = tid; e < 8 * 256; e += 256) {
        int r = e >> 8, c = e & 255;
        int gi = gi0 + r; Ash[r * 260 + c] = (gi < NN) ? A[gi * 256 + c] : 0.f;
        int gj = gj0 + r; Bsh[r * 260 + c] = (gj < NN) ? B[gj * 256 + c] : 0.f;
    }
    b1s[tid] = b1[tid];

    int tpy = tid >> 4, tpx = tid & 15;
    int p0 = tpy * 4;
    float acc[4][8];
#pragma unroll
    for (int i = 0; i < 4; ++i)
#pragma unroll
        for (int j = 0; j < 8; ++j) acc[i][j] = 0.f;

    for (int kc = 0; kc < 256; kc += 32) {
        __syncthreads();
#pragma unroll
        for (int n = 0; n < 8; ++n) {
            int e = tid + n * 256;
            int kk = e >> 6, p = e & 63;
            int pi = p >> 3, pj = p & 7;
            float v = Ash[pi * 260 + kc + kk] + Bsh[pj * 260 + kc + kk] + b1s[kc + kk];
            Vsh[kk * 68 + p] = fmaxf(v, 0.f);
        }
#pragma unroll
        for (int n = 0; n < 16; ++n) {
            int e = tid + n * 256;
            int kk = e >> 7, o = e & 127;
            W2c[kk * 132 + o] = g_W2T[(kc + kk) * 128 + o];
        }
        __syncthreads();
#pragma unroll
        for (int kk = 0; kk < 32; ++kk) {
            float a[4], b[8];
#pragma unroll
            for (int i = 0; i < 4; ++i) a[i] = Vsh[kk * 68 + p0 + i];
#pragma unroll
            for (int j = 0; j < 4; ++j) {
                b[j]     = W2c[kk * 132 + tpx * 4 + j];
                b[4 + j] = W2c[kk * 132 + 64 + tpx * 4 + j];
            }
#pragma unroll
            for (int i = 0; i < 4; ++i)
#pragma unroll
                for (int j = 0; j < 8; ++j) acc[i][j] += a[i] * b[j];
        }
    }
    __syncthreads();
#pragma unroll
    for (int j = 0; j < 4; ++j) {
        float bb0 = b2[tpx * 4 + j], bb1 = b2[64 + tpx * 4 + j];
#pragma unroll
        for (int i = 0; i < 4; ++i) {
            h2s[(p0 + i) * 132 + tpx * 4 + j]       = fmaxf(acc[i][j] + bb0, 0.f);
            h2s[(p0 + i) * 132 + 64 + tpx * 4 + j]  = fmaxf(acc[i][4 + j] + bb1, 0.f);
        }
    }
#pragma unroll
    for (int n = 0; n < 32; ++n) {
        int e = tid + n * 256;
        int k = e >> 6, o = e & 63;
        W3s[k * 68 + o] = g_W3T[k * 64 + o];
    }
    __syncthreads();

    float acc2[4][4];
#pragma unroll
    for (int i = 0; i < 4; ++i)
#pragma unroll
        for (int j = 0; j < 4; ++j) acc2[i][j] = 0.f;
    for (int k = 0; k < 128; ++k) {
        float a[4], b[4];
#pragma unroll
        for (int i = 0; i < 4; ++i) a[i] = h2s[(p0 + i) * 132 + k];
#pragma unroll
        for (int j = 0; j < 4; ++j) b[j] = W3s[k * 68 + tpx * 4 + j];
#pragma unroll
        for (int i = 0; i < 4; ++i)
#pragma unroll
            for (int j = 0; j < 4; ++j) acc2[i][j] += a[i] * b[j];
    }
    float w4v[4], b3v[4];
#pragma unroll
    for (int j = 0; j < 4; ++j) { w4v[j] = W4[tpx * 4 + j]; b3v[j] = b3[tpx * 4 + j]; }
    float partial[4];
#pragma unroll
    for (int i = 0; i < 4; ++i) {
        float p = 0.f;
#pragma unroll
        for (int j = 0; j < 4; ++j) p += fmaxf(acc2[i][j] + b3v[j], 0.f) * w4v[j];
        partial[i] = p;
    }
#pragma unroll
    for (int i = 0; i < 4; ++i)
#pragma unroll
        for (int off = 8; off; off >>= 1)
            partial[i] += __shfl_down_sync(0xffffffffu, partial[i], off, 16);
    if (tpx == 0) {
        float b4v = b4[0];
#pragma unroll
        for (int i = 0; i < 4; ++i) {
            int p = p0 + i;
            int gi = gi0 + (p >> 3), gj = gj0 + (p & 7);
            if (gi < NN && gj < NN) S[gi * NN + gj] = partial[i] + b4v;
        }
    }
}

// ------------------------- loss partials + row softmax -----------------------
__global__ void __launch_bounds__(256) row_softmax(
    const int* __restrict__ heads, float* __restrict__ out)
{
    __shared__ float srow[NN];
    __shared__ float red[256];
    int i = blockIdx.x, tid = threadIdx.x;
    int h = heads[i];
    float lp = 0.f, mx = -1e30f;
    for (int j = tid; j < NN; j += 256) {
        float v = g_S[i * NN + j];
        srow[j] = v;
        float tt = (j == h) ? 100.f : 0.f;
        float dd = v - tt; lp += dd * dd;
        mx = fmaxf(mx, v);
    }
    red[tid] = lp; __syncthreads();
    for (int o = 128; o; o >>= 1) { if (tid < o) red[tid] += red[tid + o]; __syncthreads(); }
    if (tid == 0) g_rowloss[i] = red[0];
    __syncthreads();
    red[tid] = mx; __syncthreads();
    for (int o = 128; o; o >>= 1) { if (tid < o) red[tid] = fmaxf(red[tid], red[tid + o]); __syncthreads(); }
    float m = red[0];
    __syncthreads();
    float se = 0.f;
    for (int j = tid; j < NN; j += 256) { float e = expf(srow[j] - m); srow[j] = e; se += e; }
    red[tid] = se; __syncthreads();
    for (int o = 128; o; o >>= 1) { if (tid < o) red[tid] += red[tid + o]; __syncthreads(); }
    float inv = 1.f / red[0];
    for (int j = tid; j < NN; j += 256) out[1 + i * NN + j] = srow[j] * inv;
}

__global__ void __launch_bounds__(256) finalize_loss(float* __restrict__ out) {
    __shared__ float red[256];
    int tid = threadIdx.x;
    float s = 0.f;
    for (int i = tid; i < NN; i += 256) s += g_rowloss[i];
    red[tid] = s; __syncthreads();
    for (int o = 128; o; o >>= 1) { if (tid < o) red[tid] += red[tid + o]; __syncthreads(); }
    if (tid == 0) out[0] = red[0] / ((float)NN * (float)NN);
}

// ------------------------- launch --------------------------------------------
extern "C" void kernel_launch(void* const* d_in, const int* in_sizes, int n_in,
                              void* d_out, int out_size) {
    const float* x     = (const float*)d_in[0];
    const int*   heads = (const int*)d_in[1];
    const float* Wih0  = (const float*)d_in[2];   // (2,2048,345)
    const float* Whh0  = (const float*)d_in[3];   // (2,2048,512)
    const float* b0    = (const float*)d_in[4];   // (2,2048)
    const float* Wih_r = (const float*)d_in[5];   // (3,2,2048,1024)
    const float* Whh_r = (const float*)d_in[6];   // (3,2,2048,512)
    const float* b_r   = (const float*)d_in[7];   // (3,2,2048)
    const float* W1    = (const float*)d_in[8];   // (256,2048)
    const float* b1    = (const float*)d_in[9];
    const float* W2    = (const float*)d_in[10];  // (128,256)
    const float* b2    = (const float*)d_in[11];
    const float* W3    = (const float*)d_in[12];  // (64,128)
    const float* b3    = (const float*)d_in[13];
    const float* W4    = (const float*)d_in[14];  // (1,64)
    const float* b4    = (const float*)d_in[15];
    float* out = (float*)d_out;

    float* zin; cudaGetSymbolAddress((void**)&zin, g_zin);
    float* seq; cudaGetSymbolAddress((void**)&seq, g_seq);
    float* gA;  cudaGetSymbolAddress((void**)&gA, g_A);
    float* gB;  cudaGetSymbolAddress((void**)&gB, g_B);
    float* gS;  cudaGetSymbolAddress((void**)&gS, g_S);
    float* seq0 = seq;
    float* seq1 = seq + SEQL * 1024;

    static int smem_set = 0;
    const int PAIR_SMEM = (8*260*2 + 256 + 32*68 + 32*132 + 64*132 + 128*68) * 4;
    if (!smem_set) {
        cudaFuncSetAttribute(pair_mlp, cudaFuncAttributeMaxDynamicSharedMemorySize, PAIR_SMEM);
        smem_set = 1;
    }

    prep_transpose<<<128, 256>>>(W2, W3);

    // ---- layer 0 ----
    fill_sentinel<<<SEQL, 1024>>>(seq0);
    gemm_xt<<<dim3(64, 8), 256>>>(x, Wih0, b0, zin, 512, 4096, EMBD, EMBD, EMBD, 4096, 0);
    lstm_layer<<<128, 256>>>(zin, Whh0, seq0);

    // ---- layers 1..3 ----
    for (int l = 1; l <= 3; ++l) {
        const float* Xin = (l & 1) ? seq0 : seq1;
        float* Yout = (l & 1) ? seq1 : seq0;
        const float* Wih = Wih_r + (size_t)(l - 1) * 2 * 2048 * 1024;
        const float* Whh = Whh_r + (size_t)(l - 1) * 2 * 2048 * 512;
        const float* bb  = b_r + (size_t)(l - 1) * 4096;
        fill_sentinel<<<SEQL, 1024>>>(Yout);
        gemm_xt<<<dim3(64, 8), 256>>>(Xin, Wih, bb, zin, 512, 4096, 1024, 1024, 1024, 4096, 0);
        lstm_layer<<<128, 256>>>(zin, Whh, Yout);
    }

    // ---- A/B projections (avail = [zeros; seq1], shift=1) ----
    gemm_xt<<<dim3(4, 9), 256>>>(seq1, W1,        nullptr, gA, NN, 256, 1024, 1024, 2048, 256, 1);
    gemm_xt<<<dim3(4, 9), 256>>>(seq1, W1 + 1024, nullptr, gB, NN, 256, 1024, 1024, 2048, 256, 1);

    // ---- pairwise scorer ----
    pair_mlp<<<dim3(65, 65), 256, PAIR_SMEM>>>(gA, gB, b1, b2, b3, W4, b4, gS);

    // ---- loss + softmax + output ----
    row_softmax<<<NN, 256>>>(heads, out);
    finalize_loss<<<1, 256>>>(out);
}